// round 13
// baseline (speedup 1.0000x reference)
#include <cuda_runtime.h>

#define NN   20000
#define NE   160000
#define INF  16
#define H1   512
#define H2   1024
#define OUTF 16

#define GRID 148                 // 1 block per SM, all resident
#define BLK  1024
#define NT   (GRID * BLK)        // 151552 threads
#define WPB  (BLK / 32)          // 32 warps/block
#define NW   (GRID * WPB)        // 4736 warps

typedef unsigned long long ull;

// Scratch (device globals; zero-initialized at module load)
__device__ __align__(128) float  g_deg[NN];      // zeroed at load; reset in S7
__device__ __align__(128) float  g_dinv[NN];
__device__ __align__(128) float4 g_y1[NN * 4];   // RED acc: sum_in dinv_s*x_s (zeroed S0)
__device__ __align__(128) float4 g_ts[NN * 4];   // dinv_i * t_i  (STG'd in S4)
__device__ __align__(128) ull    g_wf2[8 * H1];  // [8 cp][512 j]: (Wf[j][2cp],Wf[j][2cp+1])
__device__ __align__(128) float  g_cvec[32];     // b2@Wl + bl

// Grid barrier: monotone counters, never reset -> graph-replay safe
__device__ unsigned g_arrive[8];
__device__ unsigned g_release[8];

__device__ __forceinline__ void grid_sync(int b) {
    __syncthreads();
    if (threadIdx.x == 0) {
        __threadfence();
        unsigned old = atomicAdd(&g_arrive[b], 1u);
        unsigned target = old / (unsigned)GRID + 1u;
        if (old % (unsigned)GRID == (unsigned)(GRID - 1))
            atomicAdd(&g_release[b], 1u);
        while (*(volatile unsigned*)&g_release[b] < target) {}
        __threadfence();
    }
    __syncthreads();
}

// ---- f32x2 helpers ----
__device__ __forceinline__ ull pack2(float a) {
    ull r; asm("mov.b64 %0, {%1, %1};" : "=l"(r) : "f"(a)); return r;
}
__device__ __forceinline__ ull packab(float a, float b) {
    ull r; asm("mov.b64 %0, {%1, %2};" : "=l"(r) : "f"(a), "f"(b)); return r;
}
__device__ __forceinline__ ull fma2(ull a, ull b, ull c) {
    ull d; asm("fma.rn.f32x2 %0, %1, %2, %3;" : "=l"(d) : "l"(a), "l"(b), "l"(c));
    return d;
}
__device__ __forceinline__ float2 unpack2(ull v) {
    float2 f; asm("mov.b64 {%0, %1}, %2;" : "=f"(f.x), "=f"(f.y) : "l"(v));
    return f;
}
__device__ __forceinline__ void redv4(float* p, float4 v) {
    asm volatile("red.global.add.v4.f32 [%0], {%1,%2,%3,%4};"
                 :: "l"(p), "f"(v.x), "f"(v.y), "f"(v.z), "f"(v.w) : "memory");
}

extern "C" __global__ void __launch_bounds__(BLK, 1)
gcn_persistent(const float* __restrict__ x,  const int* __restrict__ g,
               const float* __restrict__ W1, const float* __restrict__ b1,
               const float* __restrict__ W2, const float* __restrict__ b2,
               const float* __restrict__ Wl, const float* __restrict__ bl,
               float* __restrict__ out)
{
    extern __shared__ ull smem_u[];
    ull* sW1u = smem_u;          // 32 KB: W1 row-major [16][512]
    ull* sWf2 = smem_u + 4096;   // 32 KB: [8 cp][512 j] ull pairs
    const ulonglong2* sW1p = (const ulonglong2*)sW1u;

    const int tid  = threadIdx.x;
    const int gid  = blockIdx.x * BLK + tid;
    const int wid  = tid >> 5, lane = tid & 31;
    const int gw   = blockIdx.x * WPB + wid;

    // ===== S0: stage W1; zero y1 & out; deg atomics; Wf=W2@Wl; cvec ========
    const ull* W1v = (const ull*)W1;
    for (int i = tid; i < 4096; i += BLK) sW1u[i] = W1v[i];

    {   // zero RED accumulators
        const float4 z = make_float4(0.f, 0.f, 0.f, 0.f);
        float4* out4 = (float4*)out;
        for (int i = gid; i < NN * 4; i += NT) { g_y1[i] = z; out4[i] = z; }
    }

    // fused weight Wf = W2@Wl spread over 128 blocks x 4 warps (flatten skew)
    if (wid < 4 && blockIdx.x < 128) {
        const int j = blockIdx.x * 4 + wid;   // W2 row index (H1 of them)
        float acc[16];
#pragma unroll
        for (int c = 0; c < 16; c++) acc[c] = 0.0f;
        const float* w2r = W2 + (size_t)j * H2;
#pragma unroll 4
        for (int jj = 0; jj < H2 / 32; jj++) {
            int m = jj * 32 + lane;
            float w2 = __ldg(w2r + m);
            const float4* wl = (const float4*)(Wl + (size_t)m * OUTF);
            float4 a = __ldg(wl), b = __ldg(wl + 1), c4 = __ldg(wl + 2), d4 = __ldg(wl + 3);
            acc[0]  += w2 * a.x;  acc[1]  += w2 * a.y;  acc[2]  += w2 * a.z;  acc[3]  += w2 * a.w;
            acc[4]  += w2 * b.x;  acc[5]  += w2 * b.y;  acc[6]  += w2 * b.z;  acc[7]  += w2 * b.w;
            acc[8]  += w2 * c4.x; acc[9]  += w2 * c4.y; acc[10] += w2 * c4.z; acc[11] += w2 * c4.w;
            acc[12] += w2 * d4.x; acc[13] += w2 * d4.y; acc[14] += w2 * d4.z; acc[15] += w2 * d4.w;
        }
#pragma unroll
        for (int off = 16; off; off >>= 1)
#pragma unroll
            for (int c = 0; c < 16; c++) acc[c] += __shfl_xor_sync(0xFFFFFFFFu, acc[c], off);
        if (lane < 8)   // lane L writes c-pair (2L, 2L+1) for this j
            g_wf2[lane * H1 + j] = packab(acc[2 * lane], acc[2 * lane + 1]);
    } else if (blockIdx.x == 128 && wid == 0) {
        int c = lane & 15, half = lane >> 4;
        float s = 0.0f;
        for (int j = half * (H2 / 2); j < (half + 1) * (H2 / 2); j++)
            s += __ldg(b2 + j) * __ldg(Wl + (size_t)j * OUTF + c);
        s += __shfl_xor_sync(0xFFFFFFFFu, s, 16);
        if (lane < 16) g_cvec[c] = s + __ldg(bl + c);
    }

    // degree atomics overlap with fusew (deg zero at entry)
    for (int e = gid; e < NE; e += NT)
        atomicAdd(&g_deg[g[NE + e]], 1.0f);
    grid_sync(0);

    // stage Wf2 into smem (stable after sync0)
    for (int i = tid; i < 4096; i += BLK)
        sWf2[i] = __ldcg(&g_wf2[i]);

    // ===== S1: store dinv; edge REDs  y1[d] += rsqrt(deg[s]+1)*x[s] ========
    for (int i = gid; i < NN; i += NT)
        g_dinv[i] = rsqrtf(__ldcg(&g_deg[i]) + 1.0f);

    for (int e = gid; e < NE; e += NT) {
        int s = g[e], d = g[NE + e];
        float dvs = rsqrtf(__ldcg(&g_deg[s]) + 1.0f);
        const float4* xr = (const float4*)(x + (size_t)s * INF);
        float* o = (float*)&g_y1[d * 4];
#pragma unroll
        for (int q = 0; q < 4; q++) {
            float4 v = __ldg(xr + q);
            redv4(o + q * 4, make_float4(dvs * v.x, dvs * v.y, dvs * v.z, dvs * v.w));
        }
    }
    grid_sync(1);

    // ===== S4: MLP, 2 nodes/warp; stage2 f32x2 c-pair packed ===============
    // lane L owns hidden units j = t*128 + L*4 + q; y = dinv*(y1e + dinv*x)
    const ulonglong2* b1v = (const ulonglong2*)b1;
    const int ln = lane & 7;
    const int myn = ln >> 2;              // which of the 2 nodes this lane carries
    for (int grp = gw; grp < NN / 2; grp += NW) {
        const int n0 = grp * 2;
        const int nd = n0 + myn;
        float4 yv = __ldcg(&g_y1[nd * 4 + (ln & 3)]);
        float4 xv = __ldg((const float4*)(x + (size_t)nd * INF) + (ln & 3));
        float  dv = __ldcg(&g_dinv[nd]);
        float dv2 = dv * dv;
        yv.x = dv * yv.x + dv2 * xv.x; yv.y = dv * yv.y + dv2 * xv.y;
        yv.z = dv * yv.z + dv2 * xv.z; yv.w = dv * yv.w + dv2 * xv.w;

        // stage 1 (f32x2)
        ull h2[2][8];
#pragma unroll
        for (int t = 0; t < 4; t++) {
            ulonglong2 bv = b1v[t * 32 + lane];
#pragma unroll
            for (int n = 0; n < 2; n++) { h2[n][t * 2] = bv.x; h2[n][t * 2 + 1] = bv.y; }
        }
#pragma unroll
        for (int k = 0; k < 16; k++) {
            float comp = (k & 3) == 0 ? yv.x : (k & 3) == 1 ? yv.y : (k & 3) == 2 ? yv.z : yv.w;
            ull yp[2];
#pragma unroll
            for (int n = 0; n < 2; n++)
                yp[n] = pack2(__shfl_sync(0xFFFFFFFFu, comp, n * 4 + (k >> 2)));
#pragma unroll
            for (int t = 0; t < 4; t++) {
                ulonglong2 wv = sW1p[k * 128 + t * 32 + lane];  // LDS.128
#pragma unroll
                for (int n = 0; n < 2; n++) {
                    h2[n][t * 2]     = fma2(yp[n], wv.x, h2[n][t * 2]);
                    h2[n][t * 2 + 1] = fma2(yp[n], wv.y, h2[n][t * 2 + 1]);
                }
            }
        }
        // relu -> packed broadcast pairs hp[n][t][comp]
        ull acc2[2][8];
#pragma unroll
        for (int m = 0; m < 2; m++)
#pragma unroll
            for (int cp = 0; cp < 8; cp++) acc2[m][cp] = 0ull;

#pragma unroll
        for (int t = 0; t < 4; t++) {
            const int j0 = t * 128 + lane * 4;
            ull hp[2][4];
#pragma unroll
            for (int n = 0; n < 2; n++) {
                float2 a = unpack2(h2[n][t * 2]), b = unpack2(h2[n][t * 2 + 1]);
                hp[n][0] = pack2(fmaxf(a.x, 0.0f));
                hp[n][1] = pack2(fmaxf(a.y, 0.0f));
                hp[n][2] = pack2(fmaxf(b.x, 0.0f));
                hp[n][3] = pack2(fmaxf(b.y, 0.0f));
            }
#pragma unroll
            for (int cp = 0; cp < 8; cp++) {
                ulonglong2 wA = *(const ulonglong2*)(sWf2 + cp * H1 + j0);      // j0,j0+1
                ulonglong2 wB = *(const ulonglong2*)(sWf2 + cp * H1 + j0 + 2);  // j0+2,j0+3
#pragma unroll
                for (int m = 0; m < 2; m++) {
                    acc2[m][cp] = fma2(hp[m][0], wA.x, acc2[m][cp]);
                    acc2[m][cp] = fma2(hp[m][1], wA.y, acc2[m][cp]);
                    acc2[m][cp] = fma2(hp[m][2], wB.x, acc2[m][cp]);
                    acc2[m][cp] = fma2(hp[m][3], wB.y, acc2[m][cp]);
                }
            }
        }

        // unpack to acc[m][c]
        float acc[2][16];
#pragma unroll
        for (int m = 0; m < 2; m++)
#pragma unroll
            for (int cp = 0; cp < 8; cp++) {
                float2 u = unpack2(acc2[m][cp]);
                acc[m][2 * cp] = u.x; acc[m][2 * cp + 1] = u.y;
            }

        // log-fold reduction: 31 shuffles; lane L ends with element n0*16+L
        float v[16];
        {
            int bit = (lane >> 4) & 1;   // fold node dimension
#pragma unroll
            for (int i = 0; i < 16; i++) {
                float give = bit ? acc[0][i] : acc[1][i];
                float keep = bit ? acc[1][i] : acc[0][i];
                v[i] = keep + __shfl_xor_sync(0xFFFFFFFFu, give, 16);
            }
        }
#pragma unroll
        for (int o = 8; o >= 1; o >>= 1) {   // fold c bits 3..0
            int bit = (lane / o) & 1;
#pragma unroll
            for (int i = 0; i < o; i++) {
                float give = bit ? v[i] : v[i + o];
                float keep = bit ? v[i + o] : v[i];
                v[i] = keep + __shfl_xor_sync(0xFFFFFFFFu, give, o);
            }
        }
        float dvn = __shfl_sync(0xFFFFFFFFu, dv, (lane >> 4) << 2);
        ((float*)g_ts)[(size_t)n0 * OUTF + lane] = dvn * v[0];  // coalesced 128B
    }
    grid_sync(2);

    // ===== S6: out[d] += ts[s]  (vector REDs; out zeroed in S0) ============
    for (int e = gid; e < NE; e += NT) {
        int s = g[e], d = g[NE + e];
        const float4* tr = &g_ts[s * 4];
        float* o = out + (size_t)d * OUTF;
#pragma unroll
        for (int q = 0; q < 4; q++) redv4(o + q * 4, __ldcg(tr + q));
    }
    grid_sync(3);

    // ===== S7: out = dinv*(out + ts_self) + cvec; reset deg ================
    float4* out4 = (float4*)out;
    for (int i = gid; i < NN; i += NT) {
        float dv = __ldcg(&g_dinv[i]);
        __stcg(&g_deg[i], 0.0f);                 // reset for next replay
        const float4* cv = (const float4*)g_cvec;
#pragma unroll
        for (int q = 0; q < 4; q++) {
            float4 o = __ldcg(&out4[i * 4 + q]);
            float4 t = __ldcg(&g_ts[i * 4 + q]);
            float4 c = cv[q];
            out4[i * 4 + q] = make_float4(dv * (o.x + t.x) + c.x,
                                          dv * (o.y + t.y) + c.y,
                                          dv * (o.z + t.z) + c.z,
                                          dv * (o.w + t.w) + c.w);
        }
    }
}

// ---------------------------------------------------------------- launch
extern "C" void kernel_launch(void* const* d_in, const int* in_sizes, int n_in,
                              void* d_out, int out_size) {
    const float* x  = (const float*)d_in[0];
    const int*   g  = (const int*)d_in[1];
    const float* W1 = (const float*)d_in[2];
    const float* b1 = (const float*)d_in[3];
    const float* W2 = (const float*)d_in[4];
    const float* b2 = (const float*)d_in[5];
    const float* Wl = (const float*)d_in[6];
    const float* bl = (const float*)d_in[7];
    float* out = (float*)d_out;

    cudaFuncSetAttribute(gcn_persistent,
                         cudaFuncAttributeMaxDynamicSharedMemorySize, 65536);
    gcn_persistent<<<GRID, BLK, 65536>>>(x, g, W1, b1, W2, b2, Wl, bl, out);
}

// round 15
// speedup vs baseline: 1.0797x; 1.0797x over previous
#include <cuda_runtime.h>

#define NN   20000
#define NE   160000
#define INF  16
#define H1   512
#define H2   1024
#define OUTF 16

#define GRID 296                 // 2 blocks per SM, all resident
#define BLK  512
#define NT   (GRID * BLK)        // 151552 threads
#define WPB  (BLK / 32)          // 16 warps/block
#define NW   (GRID * WPB)        // 4736 warps

typedef unsigned long long ull;

// Scratch (device globals; zero-initialized at module load)
__device__ __align__(128) float  g_deg[NN];      // zeroed at load; re-zeroed in S2
__device__ __align__(128) float  g_dinv[NN];
__device__ __align__(128) float4 g_xs[NN * 4];   // dinv[i] * x[i]
__device__ __align__(128) float4 g_y1[NN * 4];   // xs[self] + sum_in xs[s]
__device__ __align__(128) float4 g_t[NN * 4];    // dinv * MLP(dinv*y1)
__device__ __align__(128) ull    g_wf2[8 * H1];  // [8 cp][512 j]: (Wf[j][2cp],Wf[j][2cp+1])
__device__ __align__(128) float  g_cvec[32];     // b2@Wl + bl

// Grid barrier: monotone counters, never reset -> graph-replay safe
__device__ unsigned g_arrive[8];
__device__ unsigned g_release[8];

__device__ __forceinline__ void grid_sync(int b) {
    __syncthreads();
    if (threadIdx.x == 0) {
        __threadfence();
        unsigned old = atomicAdd(&g_arrive[b], 1u);
        unsigned target = old / (unsigned)GRID + 1u;
        if (old % (unsigned)GRID == (unsigned)(GRID - 1))
            atomicAdd(&g_release[b], 1u);
        while (*(volatile unsigned*)&g_release[b] < target) {}
        __threadfence();
    }
    __syncthreads();
}

// ---- f32x2 helpers ----
__device__ __forceinline__ ull pack2(float a) {
    ull r; asm("mov.b64 %0, {%1, %1};" : "=l"(r) : "f"(a)); return r;
}
__device__ __forceinline__ ull packab(float a, float b) {
    ull r; asm("mov.b64 %0, {%1, %2};" : "=l"(r) : "f"(a), "f"(b)); return r;
}
__device__ __forceinline__ ull fma2(ull a, ull b, ull c) {
    ull d; asm("fma.rn.f32x2 %0, %1, %2, %3;" : "=l"(d) : "l"(a), "l"(b), "l"(c));
    return d;
}
__device__ __forceinline__ float2 unpack2(ull v) {
    float2 f; asm("mov.b64 {%0, %1}, %2;" : "=f"(f.x), "=f"(f.y) : "l"(v));
    return f;
}
__device__ __forceinline__ void redv4(float* p, float4 v) {
    asm volatile("red.global.add.v4.f32 [%0], {%1,%2,%3,%4};"
                 :: "l"(p), "f"(v.x), "f"(v.y), "f"(v.z), "f"(v.w) : "memory");
}

extern "C" __global__ void __launch_bounds__(BLK, 2)
gcn_persistent(const float* __restrict__ x,  const int* __restrict__ g,
               const float* __restrict__ W1, const float* __restrict__ b1,
               const float* __restrict__ W2, const float* __restrict__ b2,
               const float* __restrict__ Wl, const float* __restrict__ bl,
               float* __restrict__ out)
{
    extern __shared__ ull smem_u[];
    ull* sW1u = smem_u;          // 32 KB: W1 row-major [16][512]
    ull* sWf2 = smem_u + 4096;   // 32 KB: [8 cp][512 j] ull pairs
    const ulonglong2* sW1p = (const ulonglong2*)sW1u;

    const int tid  = threadIdx.x;
    const int gid  = blockIdx.x * BLK + tid;
    const int wid  = tid >> 5, lane = tid & 31;
    const int gw   = blockIdx.x * WPB + wid;

    // ===== S0: stage W1; deg atomics; Wf=W2@Wl (warp/j-row); cvec ==========
    const ull* W1v = (const ull*)W1;
    for (int i = tid; i < 4096; i += BLK) sW1u[i] = W1v[i];

    if (gw < H1) {  // fused weight: one warp per j-row of W2
        const int j = gw;
        float acc[16];
#pragma unroll
        for (int c = 0; c < 16; c++) acc[c] = 0.0f;
        const float* w2r = W2 + (size_t)j * H2;
#pragma unroll 4
        for (int jj = 0; jj < H2 / 32; jj++) {
            int m = jj * 32 + lane;
            float w2 = __ldg(w2r + m);
            const float4* wl = (const float4*)(Wl + (size_t)m * OUTF);
            float4 a = __ldg(wl), b = __ldg(wl + 1), c4 = __ldg(wl + 2), d4 = __ldg(wl + 3);
            acc[0]  += w2 * a.x;  acc[1]  += w2 * a.y;  acc[2]  += w2 * a.z;  acc[3]  += w2 * a.w;
            acc[4]  += w2 * b.x;  acc[5]  += w2 * b.y;  acc[6]  += w2 * b.z;  acc[7]  += w2 * b.w;
            acc[8]  += w2 * c4.x; acc[9]  += w2 * c4.y; acc[10] += w2 * c4.z; acc[11] += w2 * c4.w;
            acc[12] += w2 * d4.x; acc[13] += w2 * d4.y; acc[14] += w2 * d4.z; acc[15] += w2 * d4.w;
        }
#pragma unroll
        for (int off = 16; off; off >>= 1)
#pragma unroll
            for (int c = 0; c < 16; c++) acc[c] += __shfl_xor_sync(0xFFFFFFFFu, acc[c], off);
        if (lane < 8)   // lane L -> c-pair (2L, 2L+1)
            g_wf2[lane * H1 + j] = packab(acc[2 * lane], acc[2 * lane + 1]);
    } else if (gw == NW - 1) {
        int c = lane & 15, half = lane >> 4;
        float s = 0.0f;
        for (int j = half * (H2 / 2); j < (half + 1) * (H2 / 2); j++)
            s += __ldg(b2 + j) * __ldg(Wl + (size_t)j * OUTF + c);
        s += __shfl_xor_sync(0xFFFFFFFFu, s, 16);
        if (lane < 16) g_cvec[c] = s + __ldg(bl + c);
    }

    // degree atomics overlap with fusew (deg zero at entry)
    for (int e = gid; e < NE; e += NT)
        atomicAdd(&g_deg[g[NE + e]], 1.0f);
    grid_sync(0);

    // stage Wf2 into smem (stable after sync0)
    for (int i = tid; i < 4096; i += BLK)
        sWf2[i] = __ldcg(&g_wf2[i]);

    // ===== S2: dinv = rsqrt(deg+1); xs = dinv*x; y1 = xs; deg := 0 =========
    for (int i = gid; i < NN; i += NT) {
        float dv = rsqrtf(__ldcg(&g_deg[i]) + 1.0f);   // +1 = self-loop
        __stcg(&g_deg[i], 0.0f);                       // reset for next replay
        g_dinv[i] = dv;
        const float4* xr = (const float4*)(x + (size_t)i * INF);
#pragma unroll
        for (int q = 0; q < 4; q++) {
            float4 v = __ldg(xr + q);
            float4 s = make_float4(dv * v.x, dv * v.y, dv * v.z, dv * v.w);
            g_xs[i * 4 + q] = s;
            g_y1[i * 4 + q] = s;
        }
    }
    grid_sync(1);

    // ===== S3: y1[d] += xs[s]  (vector REDs) ===============================
    for (int e = gid; e < NE; e += NT) {
        int s = g[e], d = g[NE + e];
        const float4* xr = &g_xs[s * 4];
        float* o = (float*)&g_y1[d * 4];
#pragma unroll
        for (int q = 0; q < 4; q++) redv4(o + q * 4, __ldcg(xr + q));
    }
    grid_sync(2);

    // ===== S4: MLP, 2 nodes/warp; stage-2 f32x2 c-pair packed ==============
    // lane L owns hidden units j = t*128 + L*4 + q; y via shuffle.
    const ulonglong2* b1v = (const ulonglong2*)b1;
    const int ln = lane & 7;
    const int myn = ln >> 2;              // which of the 2 nodes this lane carries
    for (int grp = gw; grp < NN / 2; grp += NW) {
        const int n0 = grp * 2;
        float4 yv = __ldcg(&g_y1[(n0 + myn) * 4 + (ln & 3)]);
        float  dv = __ldcg(&g_dinv[n0 + myn]);
        yv.x *= dv; yv.y *= dv; yv.z *= dv; yv.w *= dv;   // y_true = dinv * y1

        // stage 1 (f32x2)
        ull h2[2][8];
#pragma unroll
        for (int t = 0; t < 4; t++) {
            ulonglong2 bv = b1v[t * 32 + lane];
#pragma unroll
            for (int n = 0; n < 2; n++) { h2[n][t * 2] = bv.x; h2[n][t * 2 + 1] = bv.y; }
        }
#pragma unroll
        for (int k = 0; k < 16; k++) {
            float comp = (k & 3) == 0 ? yv.x : (k & 3) == 1 ? yv.y : (k & 3) == 2 ? yv.z : yv.w;
            ull yp[2];
#pragma unroll
            for (int n = 0; n < 2; n++)
                yp[n] = pack2(__shfl_sync(0xFFFFFFFFu, comp, n * 4 + (k >> 2)));
#pragma unroll
            for (int t = 0; t < 4; t++) {
                ulonglong2 wv = sW1p[k * 128 + t * 32 + lane];  // LDS.128
#pragma unroll
                for (int n = 0; n < 2; n++) {
                    h2[n][t * 2]     = fma2(yp[n], wv.x, h2[n][t * 2]);
                    h2[n][t * 2 + 1] = fma2(yp[n], wv.y, h2[n][t * 2 + 1]);
                }
            }
        }

        // stage 2: relu + packed f32x2 over c-pairs; weights shared by nodes
        ull acc2[2][8];
#pragma unroll
        for (int m = 0; m < 2; m++)
#pragma unroll
            for (int cp = 0; cp < 8; cp++) acc2[m][cp] = 0ull;

#pragma unroll
        for (int t = 0; t < 4; t++) {
            const int j0 = t * 128 + lane * 4;
            ull hp[2][4];
#pragma unroll
            for (int n = 0; n < 2; n++) {
                float2 a = unpack2(h2[n][t * 2]), b = unpack2(h2[n][t * 2 + 1]);
                hp[n][0] = pack2(fmaxf(a.x, 0.0f));
                hp[n][1] = pack2(fmaxf(a.y, 0.0f));
                hp[n][2] = pack2(fmaxf(b.x, 0.0f));
                hp[n][3] = pack2(fmaxf(b.y, 0.0f));
            }
#pragma unroll
            for (int cp = 0; cp < 8; cp++) {
                ulonglong2 wA = *(const ulonglong2*)(sWf2 + cp * H1 + j0);      // j0,j0+1
                ulonglong2 wB = *(const ulonglong2*)(sWf2 + cp * H1 + j0 + 2);  // j0+2,j0+3
#pragma unroll
                for (int m = 0; m < 2; m++) {
                    acc2[m][cp] = fma2(hp[m][0], wA.x, acc2[m][cp]);
                    acc2[m][cp] = fma2(hp[m][1], wA.y, acc2[m][cp]);
                    acc2[m][cp] = fma2(hp[m][2], wB.x, acc2[m][cp]);
                    acc2[m][cp] = fma2(hp[m][3], wB.y, acc2[m][cp]);
                }
            }
        }

        // unpack to acc[m][c]
        float acc[2][16];
#pragma unroll
        for (int m = 0; m < 2; m++)
#pragma unroll
            for (int cp = 0; cp < 8; cp++) {
                float2 u = unpack2(acc2[m][cp]);
                acc[m][2 * cp] = u.x; acc[m][2 * cp + 1] = u.y;
            }

        // log-fold reduction: 31 shuffles; lane L ends with element n0*16+L
        float v[16];
        {
            int bit = (lane >> 4) & 1;   // fold node dimension
#pragma unroll
            for (int i = 0; i < 16; i++) {
                float give = bit ? acc[0][i] : acc[1][i];
                float keep = bit ? acc[1][i] : acc[0][i];
                v[i] = keep + __shfl_xor_sync(0xFFFFFFFFu, give, 16);
            }
        }
#pragma unroll
        for (int o = 8; o >= 1; o >>= 1) {   // fold c bits 3..0
            int bit = (lane / o) & 1;
#pragma unroll
            for (int i = 0; i < o; i++) {
                float give = bit ? v[i] : v[i + o];
                float keep = bit ? v[i + o] : v[i];
                v[i] = keep + __shfl_xor_sync(0xFFFFFFFFu, give, o);
            }
        }
        // scale by dinv of the node this lane's element belongs to
        float dvn = __shfl_sync(0xFFFFFFFFu, dv, (lane >> 4) << 2);
        float ts = dvn * v[0];
        ((float*)g_t)[(size_t)n0 * OUTF + lane] = ts;   // coalesced 128B
        out[(size_t)n0 * OUTF + lane]           = ts;   // self-loop init
    }
    grid_sync(3);

    // ===== S6: out[d] += ts[s]  (vector REDs) ==============================
    for (int e = gid; e < NE; e += NT) {
        int s = g[e], d = g[NE + e];
        const float4* tr = &g_t[s * 4];
        float* o = out + (size_t)d * OUTF;
#pragma unroll
        for (int q = 0; q < 4; q++) redv4(o + q * 4, __ldcg(tr + q));
    }
    grid_sync(4);

    // ===== S7: out = dinv[i]*out + cvec ====================================
    float4* out4 = (float4*)out;
    for (int v4i = gid; v4i < NN * 4; v4i += NT) {
        int i = v4i >> 2, q = v4i & 3;
        float dv = __ldcg(&g_dinv[i]);
        float4 o = __ldcg(&out4[v4i]);
        float4 c = __ldcg(&((const float4*)g_cvec)[q]);
        out4[v4i] = make_float4(dv * o.x + c.x, dv * o.y + c.y,
                                dv * o.z + c.z, dv * o.w + c.w);
    }
}

// ---------------------------------------------------------------- launch
extern "C" void kernel_launch(void* const* d_in, const int* in_sizes, int n_in,
                              void* d_out, int out_size) {
    const float* x  = (const float*)d_in[0];
    const int*   g  = (const int*)d_in[1];
    const float* W1 = (const float*)d_in[2];
    const float* b1 = (const float*)d_in[3];
    const float* W2 = (const float*)d_in[4];
    const float* b2 = (const float*)d_in[5];
    const float* Wl = (const float*)d_in[6];
    const float* bl = (const float*)d_in[7];
    float* out = (float*)d_out;

    cudaFuncSetAttribute(gcn_persistent,
                         cudaFuncAttributeMaxDynamicSharedMemorySize, 65536);
    gcn_persistent<<<GRID, BLK, 65536>>>(x, g, W1, b1, W2, b2, Wl, bl, out);
}

// round 16
// speedup vs baseline: 1.2786x; 1.1842x over previous
#include <cuda_runtime.h>

#define NN   20000
#define NE   160000
#define INF  16
#define H1   512
#define H2   1024
#define OUTF 16

#define GRID 296                 // 2 blocks per SM, all resident
#define BLK  512
#define NT   (GRID * BLK)        // 151552 threads
#define WPB  (BLK / 32)          // 16 warps/block
#define NW   (GRID * WPB)        // 4736 warps

typedef unsigned long long ull;

// Scratch (device globals; zero-initialized at module load)
__device__ __align__(128) float  g_deg[NN];      // zeroed at load; re-zeroed in S2
__device__ __align__(128) float  g_dinv[NN];
__device__ __align__(128) float4 g_xs[NN * 4];   // dinv[i] * x[i]
__device__ __align__(128) float4 g_y1[NN * 4];   // xs[self] + sum_in xs[s]
__device__ __align__(128) float4 g_t[NN * 4];    // dinv * MLP(dinv*y1)
__device__ __align__(128) float4 g_wfT[OUTF * H1 / 4];  // [16][512]: (W2@Wl)^T
__device__ __align__(128) float  g_cvec[32];     // b2@Wl + bl

// Grid barrier: monotone counters, never reset -> graph-replay safe
__device__ unsigned g_arrive[8];
__device__ unsigned g_release[8];

__device__ __forceinline__ void grid_sync(int b) {
    __syncthreads();
    if (threadIdx.x == 0) {
        __threadfence();
        unsigned old = atomicAdd(&g_arrive[b], 1u);
        unsigned target = old / (unsigned)GRID + 1u;
        if (old % (unsigned)GRID == (unsigned)(GRID - 1))
            atomicAdd(&g_release[b], 1u);
        while (*(volatile unsigned*)&g_release[b] < target) {}
        __threadfence();
    }
    __syncthreads();
}

// ---- f32x2 helpers ----
__device__ __forceinline__ ull pack2(float a) {
    ull r; asm("mov.b64 %0, {%1, %1};" : "=l"(r) : "f"(a)); return r;
}
__device__ __forceinline__ ull fma2(ull a, ull b, ull c) {
    ull d; asm("fma.rn.f32x2 %0, %1, %2, %3;" : "=l"(d) : "l"(a), "l"(b), "l"(c));
    return d;
}
__device__ __forceinline__ float2 unpack2(ull v) {
    float2 f; asm("mov.b64 {%0, %1}, %2;" : "=f"(f.x), "=f"(f.y) : "l"(v));
    return f;
}
__device__ __forceinline__ void redv4(float* p, float4 v) {
    asm volatile("red.global.add.v4.f32 [%0], {%1,%2,%3,%4};"
                 :: "l"(p), "f"(v.x), "f"(v.y), "f"(v.z), "f"(v.w) : "memory");
}

extern "C" __global__ void __launch_bounds__(BLK, 2)
gcn_persistent(const float* __restrict__ x,  const int* __restrict__ g,
               const float* __restrict__ W1, const float* __restrict__ b1,
               const float* __restrict__ W2, const float* __restrict__ b2,
               const float* __restrict__ Wl, const float* __restrict__ bl,
               float* __restrict__ out)
{
    extern __shared__ ull smem_u[];
    ull* sW1u = smem_u;                       // 32 KB: W1 row-major [16][512]
    float4* sWf = (float4*)(smem_u + 4096);   // 32 KB: wfT [16][512] floats
    const ulonglong2* sW1p = (const ulonglong2*)sW1u;

    const int tid  = threadIdx.x;
    const int gid  = blockIdx.x * BLK + tid;
    const int wid  = tid >> 5, lane = tid & 31;
    const int gw   = blockIdx.x * WPB + wid;

    // ===== S0: stage W1; deg atomics; Wf=W2@Wl (2 warps x 256 blocks) =====
    const ull* W1v = (const ull*)W1;
    for (int i = tid; i < 4096; i += BLK) sW1u[i] = W1v[i];

    if (wid < 2 && blockIdx.x < 256) {  // fused weight: spread to kill S0 skew
        const int j = blockIdx.x * 2 + wid;   // W2 row index, 0..511
        float acc[16];
#pragma unroll
        for (int c = 0; c < 16; c++) acc[c] = 0.0f;
        const float* w2r = W2 + (size_t)j * H2;
#pragma unroll 4
        for (int jj = 0; jj < H2 / 32; jj++) {
            int m = jj * 32 + lane;
            float w2 = __ldg(w2r + m);
            const float4* wl = (const float4*)(Wl + (size_t)m * OUTF);
            float4 a = __ldg(wl), b = __ldg(wl + 1), c4 = __ldg(wl + 2), d4 = __ldg(wl + 3);
            acc[0]  += w2 * a.x;  acc[1]  += w2 * a.y;  acc[2]  += w2 * a.z;  acc[3]  += w2 * a.w;
            acc[4]  += w2 * b.x;  acc[5]  += w2 * b.y;  acc[6]  += w2 * b.z;  acc[7]  += w2 * b.w;
            acc[8]  += w2 * c4.x; acc[9]  += w2 * c4.y; acc[10] += w2 * c4.z; acc[11] += w2 * c4.w;
            acc[12] += w2 * d4.x; acc[13] += w2 * d4.y; acc[14] += w2 * d4.z; acc[15] += w2 * d4.w;
        }
#pragma unroll
        for (int off = 16; off; off >>= 1)
#pragma unroll
            for (int c = 0; c < 16; c++) acc[c] += __shfl_xor_sync(0xFFFFFFFFu, acc[c], off);
        if (lane < 16) ((float*)g_wfT)[lane * H1 + j] = acc[lane];
    } else if (blockIdx.x == 256 && wid == 0) {
        int c = lane & 15, half = lane >> 4;
        float s = 0.0f;
        for (int j = half * (H2 / 2); j < (half + 1) * (H2 / 2); j++)
            s += __ldg(b2 + j) * __ldg(Wl + (size_t)j * OUTF + c);
        s += __shfl_xor_sync(0xFFFFFFFFu, s, 16);
        if (lane < 16) g_cvec[c] = s + __ldg(bl + c);
    }

    // degree atomics overlap with fusew (deg zero at entry)
    for (int e = gid; e < NE; e += NT)
        atomicAdd(&g_deg[g[NE + e]], 1.0f);
    grid_sync(0);

    // stage Wf into smem (stable after sync0)
    for (int i = tid; i < OUTF * H1 / 4; i += BLK)
        sWf[i] = __ldcg(&g_wfT[i]);

    // ===== S2: dinv = rsqrt(deg+1); xs = dinv*x; y1 = xs; deg := 0 =========
    for (int i = gid; i < NN; i += NT) {
        float dv = rsqrtf(__ldcg(&g_deg[i]) + 1.0f);   // +1 = self-loop
        __stcg(&g_deg[i], 0.0f);                       // reset for next replay
        g_dinv[i] = dv;
        const float4* xr = (const float4*)(x + (size_t)i * INF);
#pragma unroll
        for (int q = 0; q < 4; q++) {
            float4 v = __ldg(xr + q);
            float4 s = make_float4(dv * v.x, dv * v.y, dv * v.z, dv * v.w);
            g_xs[i * 4 + q] = s;
            g_y1[i * 4 + q] = s;
        }
    }
    grid_sync(1);

    // ===== S3: y1[d] += xs[s]  (vector REDs) ===============================
    for (int e = gid; e < NE; e += NT) {
        int s = g[e], d = g[NE + e];
        const float4* xr = &g_xs[s * 4];
        float* o = (float*)&g_y1[d * 4];
#pragma unroll
        for (int q = 0; q < 4; q++) redv4(o + q * 4, __ldcg(xr + q));
    }
    grid_sync(2);

    // ===== S4: MLP, 2 nodes/warp (validated best layout) ===================
    // lane L owns hidden units j = t*128 + L*4 + q; y via shuffle.
    const ulonglong2* b1v = (const ulonglong2*)b1;
    const int ln = lane & 7;
    const int myn = ln >> 2;              // which of the 2 nodes this lane carries
    for (int grp = gw; grp < NN / 2; grp += NW) {
        const int n0 = grp * 2;
        float4 yv = __ldcg(&g_y1[(n0 + myn) * 4 + (ln & 3)]);
        float  dv = __ldcg(&g_dinv[n0 + myn]);
        yv.x *= dv; yv.y *= dv; yv.z *= dv; yv.w *= dv;   // y_true = dinv * y1

        // stage 1 (f32x2)
        ull h2[2][8];
#pragma unroll
        for (int t = 0; t < 4; t++) {
            ulonglong2 bv = b1v[t * 32 + lane];
#pragma unroll
            for (int n = 0; n < 2; n++) { h2[n][t * 2] = bv.x; h2[n][t * 2 + 1] = bv.y; }
        }
#pragma unroll
        for (int k = 0; k < 16; k++) {
            float comp = (k & 3) == 0 ? yv.x : (k & 3) == 1 ? yv.y : (k & 3) == 2 ? yv.z : yv.w;
            ull yp[2];
#pragma unroll
            for (int n = 0; n < 2; n++)
                yp[n] = pack2(__shfl_sync(0xFFFFFFFFu, comp, n * 4 + (k >> 2)));
#pragma unroll
            for (int t = 0; t < 4; t++) {
                ulonglong2 wv = sW1p[k * 128 + t * 32 + lane];  // LDS.128
#pragma unroll
                for (int n = 0; n < 2; n++) {
                    h2[n][t * 2]     = fma2(yp[n], wv.x, h2[n][t * 2]);
                    h2[n][t * 2 + 1] = fma2(yp[n], wv.y, h2[n][t * 2 + 1]);
                }
            }
        }
        // relu
        float4 hh[2][4];
#pragma unroll
        for (int n = 0; n < 2; n++)
#pragma unroll
            for (int t = 0; t < 4; t++) {
                float2 a = unpack2(h2[n][t * 2]), b = unpack2(h2[n][t * 2 + 1]);
                hh[n][t] = make_float4(fmaxf(a.x, 0.0f), fmaxf(a.y, 0.0f),
                                       fmaxf(b.x, 0.0f), fmaxf(b.y, 0.0f));
            }

        // stage 2: both nodes share each weight load (float4, 16B lane stride)
        float acc[2][16];
#pragma unroll
        for (int m = 0; m < 2; m++)
#pragma unroll
            for (int c = 0; c < 16; c++) acc[m][c] = 0.0f;
#pragma unroll
        for (int c = 0; c < 16; c++)
#pragma unroll
            for (int t = 0; t < 4; t++) {
                float4 w = sWf[c * 128 + t * 32 + lane];  // conflict-free LDS.128
#pragma unroll
                for (int m = 0; m < 2; m++) {
                    float4 h = hh[m][t];
                    acc[m][c] += h.x * w.x + h.y * w.y + h.z * w.z + h.w * w.w;
                }
            }

        // log-fold reduction: 31 shuffles; lane L ends with element n0*16+L
        float v[16];
        {
            int bit = (lane >> 4) & 1;   // fold node dimension
#pragma unroll
            for (int i = 0; i < 16; i++) {
                float give = bit ? acc[0][i] : acc[1][i];
                float keep = bit ? acc[1][i] : acc[0][i];
                v[i] = keep + __shfl_xor_sync(0xFFFFFFFFu, give, 16);
            }
        }
#pragma unroll
        for (int o = 8; o >= 1; o >>= 1) {   // fold c bits 3..0
            int bit = (lane / o) & 1;
#pragma unroll
            for (int i = 0; i < o; i++) {
                float give = bit ? v[i] : v[i + o];
                float keep = bit ? v[i + o] : v[i];
                v[i] = keep + __shfl_xor_sync(0xFFFFFFFFu, give, o);
            }
        }
        // scale by dinv of the node this lane's element belongs to
        float dvn = __shfl_sync(0xFFFFFFFFu, dv, (lane >> 4) << 2);
        float ts = dvn * v[0];
        ((float*)g_t)[(size_t)n0 * OUTF + lane] = ts;   // coalesced 128B
        out[(size_t)n0 * OUTF + lane]           = ts;   // self-loop init
    }
    grid_sync(3);

    // ===== S6: out[d] += ts[s]  (vector REDs) ==============================
    for (int e = gid; e < NE; e += NT) {
        int s = g[e], d = g[NE + e];
        const float4* tr = &g_t[s * 4];
        float* o = out + (size_t)d * OUTF;
#pragma unroll
        for (int q = 0; q < 4; q++) redv4(o + q * 4, __ldcg(tr + q));
    }
    grid_sync(4);

    // ===== S7: out = dinv[i]*out + cvec ====================================
    float4* out4 = (float4*)out;
    for (int v4i = gid; v4i < NN * 4; v4i += NT) {
        int i = v4i >> 2, q = v4i & 3;
        float dv = __ldcg(&g_dinv[i]);
        float4 o = __ldcg(&out4[v4i]);
        float4 c = __ldcg(&((const float4*)g_cvec)[q]);
        out4[v4i] = make_float4(dv * o.x + c.x, dv * o.y + c.y,
                                dv * o.z + c.z, dv * o.w + c.w);
    }
}

// ---------------------------------------------------------------- launch
extern "C" void kernel_launch(void* const* d_in, const int* in_sizes, int n_in,
                              void* d_out, int out_size) {
    const float* x  = (const float*)d_in[0];
    const int*   g  = (const int*)d_in[1];
    const float* W1 = (const float*)d_in[2];
    const float* b1 = (const float*)d_in[3];
    const float* W2 = (const float*)d_in[4];
    const float* b2 = (const float*)d_in[5];
    const float* Wl = (const float*)d_in[6];
    const float* bl = (const float*)d_in[7];
    float* out = (float*)d_out;

    cudaFuncSetAttribute(gcn_persistent,
                         cudaFuncAttributeMaxDynamicSharedMemorySize, 65536);
    gcn_persistent<<<GRID, BLK, 65536>>>(x, g, W1, b1, W2, b2, Wl, bl, out);
}

// round 17
// speedup vs baseline: 1.5174x; 1.1868x over previous
#include <cuda_runtime.h>

#define NN   20000
#define NE   160000
#define INF  16
#define H1   512
#define H2   1024
#define OUTF 16

#define GRID 296                 // 2 blocks per SM, all resident
#define BLK  512
#define NT   (GRID * BLK)        // 151552 threads
#define WPB  (BLK / 32)          // 16 warps/block
#define NW   (GRID * WPB)        // 4736 warps

typedef unsigned long long ull;

// Scratch (device globals; zero-initialized at module load)
__device__ __align__(128) float  g_deg[NN];      // zeroed at load; re-zeroed in S2
__device__ __align__(128) float  g_dinv[NN];
__device__ __align__(128) float4 g_xs[NN * 4];   // dinv[i] * x[i]
__device__ __align__(128) float4 g_y1[NN * 4];   // xs[self] + sum_in xs[s]
__device__ __align__(128) float4 g_t[NN * 4];    // raw ts = dinv * MLP(dinv*y1)
__device__ __align__(128) float4 g_wfT[OUTF * H1 / 4];  // [16][512]: (W2@Wl)^T
__device__ __align__(128) float  g_cvec[32];     // b2@Wl + bl

// Grid barrier: monotone counters, never reset -> graph-replay safe
__device__ unsigned g_arrive[8];
__device__ unsigned g_release[8];

__device__ __forceinline__ void grid_sync(int b) {
    __syncthreads();
    if (threadIdx.x == 0) {
        __threadfence();
        unsigned old = atomicAdd(&g_arrive[b], 1u);
        unsigned target = old / (unsigned)GRID + 1u;
        if (old % (unsigned)GRID == (unsigned)(GRID - 1))
            atomicAdd(&g_release[b], 1u);
        while (*(volatile unsigned*)&g_release[b] < target) {}
        __threadfence();
    }
    __syncthreads();
}

// ---- f32x2 helpers ----
__device__ __forceinline__ ull pack2(float a) {
    ull r; asm("mov.b64 %0, {%1, %1};" : "=l"(r) : "f"(a)); return r;
}
__device__ __forceinline__ ull fma2(ull a, ull b, ull c) {
    ull d; asm("fma.rn.f32x2 %0, %1, %2, %3;" : "=l"(d) : "l"(a), "l"(b), "l"(c));
    return d;
}
__device__ __forceinline__ float2 unpack2(ull v) {
    float2 f; asm("mov.b64 {%0, %1}, %2;" : "=f"(f.x), "=f"(f.y) : "l"(v));
    return f;
}
__device__ __forceinline__ void redv4(float* p, float4 v) {
    asm volatile("red.global.add.v4.f32 [%0], {%1,%2,%3,%4};"
                 :: "l"(p), "f"(v.x), "f"(v.y), "f"(v.z), "f"(v.w) : "memory");
}

extern "C" __global__ void __launch_bounds__(BLK, 2)
gcn_persistent(const float* __restrict__ x,  const int* __restrict__ g,
               const float* __restrict__ W1, const float* __restrict__ b1,
               const float* __restrict__ W2, const float* __restrict__ b2,
               const float* __restrict__ Wl, const float* __restrict__ bl,
               float* __restrict__ out)
{
    extern __shared__ ull smem_u[];
    ull* sW1u = smem_u;                       // 32 KB: W1 row-major [16][512]
    float4* sWf = (float4*)(smem_u + 4096);   // 32 KB: wfT [16][512] floats
    const ulonglong2* sW1p = (const ulonglong2*)sW1u;

    const int tid  = threadIdx.x;
    const int gid  = blockIdx.x * BLK + tid;
    const int wid  = tid >> 5, lane = tid & 31;
    const int gw   = blockIdx.x * WPB + wid;

    // ===== S0: stage W1; deg atomics; Wf=W2@Wl (2 warps x 256 blocks) =====
    const ull* W1v = (const ull*)W1;
    for (int i = tid; i < 4096; i += BLK) sW1u[i] = W1v[i];

    if (wid < 2 && blockIdx.x < 256) {  // fused weight: spread to kill S0 skew
        const int j = blockIdx.x * 2 + wid;   // W2 row index, 0..511
        float acc[16];
#pragma unroll
        for (int c = 0; c < 16; c++) acc[c] = 0.0f;
        const float* w2r = W2 + (size_t)j * H2;
#pragma unroll 4
        for (int jj = 0; jj < H2 / 32; jj++) {
            int m = jj * 32 + lane;
            float w2 = __ldg(w2r + m);
            const float4* wl = (const float4*)(Wl + (size_t)m * OUTF);
            float4 a = __ldg(wl), b = __ldg(wl + 1), c4 = __ldg(wl + 2), d4 = __ldg(wl + 3);
            acc[0]  += w2 * a.x;  acc[1]  += w2 * a.y;  acc[2]  += w2 * a.z;  acc[3]  += w2 * a.w;
            acc[4]  += w2 * b.x;  acc[5]  += w2 * b.y;  acc[6]  += w2 * b.z;  acc[7]  += w2 * b.w;
            acc[8]  += w2 * c4.x; acc[9]  += w2 * c4.y; acc[10] += w2 * c4.z; acc[11] += w2 * c4.w;
            acc[12] += w2 * d4.x; acc[13] += w2 * d4.y; acc[14] += w2 * d4.z; acc[15] += w2 * d4.w;
        }
#pragma unroll
        for (int off = 16; off; off >>= 1)
#pragma unroll
            for (int c = 0; c < 16; c++) acc[c] += __shfl_xor_sync(0xFFFFFFFFu, acc[c], off);
        if (lane < 16) ((float*)g_wfT)[lane * H1 + j] = acc[lane];
    } else if (blockIdx.x == 256 && wid == 0) {
        int c = lane & 15, half = lane >> 4;
        float s = 0.0f;
        for (int j = half * (H2 / 2); j < (half + 1) * (H2 / 2); j++)
            s += __ldg(b2 + j) * __ldg(Wl + (size_t)j * OUTF + c);
        s += __shfl_xor_sync(0xFFFFFFFFu, s, 16);
        if (lane < 16) g_cvec[c] = s + __ldg(bl + c);
    }

    // degree atomics overlap with fusew (deg zero at entry)
    for (int e = gid; e < NE; e += NT)
        atomicAdd(&g_deg[g[NE + e]], 1.0f);
    grid_sync(0);

    // stage Wf into smem (stable after sync0)
    for (int i = tid; i < OUTF * H1 / 4; i += BLK)
        sWf[i] = __ldcg(&g_wfT[i]);

    // ===== S2: dinv = rsqrt(deg+1); xs = dinv*x; y1 = xs; deg := 0 =========
    for (int i = gid; i < NN; i += NT) {
        float dv = rsqrtf(__ldcg(&g_deg[i]) + 1.0f);   // +1 = self-loop
        __stcg(&g_deg[i], 0.0f);                       // reset for next replay
        g_dinv[i] = dv;
        const float4* xr = (const float4*)(x + (size_t)i * INF);
#pragma unroll
        for (int q = 0; q < 4; q++) {
            float4 v = __ldg(xr + q);
            float4 s = make_float4(dv * v.x, dv * v.y, dv * v.z, dv * v.w);
            g_xs[i * 4 + q] = s;
            g_y1[i * 4 + q] = s;
        }
    }
    grid_sync(1);

    // ===== S3: y1[d] += xs[s]  (quad-level items: 4 lanes per edge) ========
    for (int it = gid; it < NE * 4; it += NT) {
        int e = it >> 2, q = it & 3;
        int s = g[e], d = g[NE + e];          // 4-lane broadcast loads
        float4 v = __ldcg(&g_xs[s * 4 + q]);  // 64B-contiguous per edge
        redv4((float*)&g_y1[d * 4 + q], v);
    }
    grid_sync(2);

    // ===== S4: MLP, 2 nodes/warp (validated best layout) ===================
    // lane L owns hidden units j = t*128 + L*4 + q; y via shuffle.
    const ulonglong2* b1v = (const ulonglong2*)b1;
    const float cv_lane = __ldcg(&g_cvec[lane & 15]);   // hoisted bias element
    const int ln = lane & 7;
    const int myn = ln >> 2;              // which of the 2 nodes this lane carries
    for (int grp = gw; grp < NN / 2; grp += NW) {
        const int n0 = grp * 2;
        float4 yv = __ldcg(&g_y1[(n0 + myn) * 4 + (ln & 3)]);
        float  dv = __ldcg(&g_dinv[n0 + myn]);
        yv.x *= dv; yv.y *= dv; yv.z *= dv; yv.w *= dv;   // y_true = dinv * y1

        // stage 1 (f32x2)
        ull h2[2][8];
#pragma unroll
        for (int t = 0; t < 4; t++) {
            ulonglong2 bv = b1v[t * 32 + lane];
#pragma unroll
            for (int n = 0; n < 2; n++) { h2[n][t * 2] = bv.x; h2[n][t * 2 + 1] = bv.y; }
        }
#pragma unroll
        for (int k = 0; k < 16; k++) {
            float comp = (k & 3) == 0 ? yv.x : (k & 3) == 1 ? yv.y : (k & 3) == 2 ? yv.z : yv.w;
            ull yp[2];
#pragma unroll
            for (int n = 0; n < 2; n++)
                yp[n] = pack2(__shfl_sync(0xFFFFFFFFu, comp, n * 4 + (k >> 2)));
#pragma unroll
            for (int t = 0; t < 4; t++) {
                ulonglong2 wv = sW1p[k * 128 + t * 32 + lane];  // LDS.128
#pragma unroll
                for (int n = 0; n < 2; n++) {
                    h2[n][t * 2]     = fma2(yp[n], wv.x, h2[n][t * 2]);
                    h2[n][t * 2 + 1] = fma2(yp[n], wv.y, h2[n][t * 2 + 1]);
                }
            }
        }
        // relu
        float4 hh[2][4];
#pragma unroll
        for (int n = 0; n < 2; n++)
#pragma unroll
            for (int t = 0; t < 4; t++) {
                float2 a = unpack2(h2[n][t * 2]), b = unpack2(h2[n][t * 2 + 1]);
                hh[n][t] = make_float4(fmaxf(a.x, 0.0f), fmaxf(a.y, 0.0f),
                                       fmaxf(b.x, 0.0f), fmaxf(b.y, 0.0f));
            }

        // stage 2: both nodes share each weight load (float4, 16B lane stride)
        float acc[2][16];
#pragma unroll
        for (int m = 0; m < 2; m++)
#pragma unroll
            for (int c = 0; c < 16; c++) acc[m][c] = 0.0f;
#pragma unroll
        for (int c = 0; c < 16; c++)
#pragma unroll
            for (int t = 0; t < 4; t++) {
                float4 w = sWf[c * 128 + t * 32 + lane];  // conflict-free LDS.128
#pragma unroll
                for (int m = 0; m < 2; m++) {
                    float4 h = hh[m][t];
                    acc[m][c] += h.x * w.x + h.y * w.y + h.z * w.z + h.w * w.w;
                }
            }

        // log-fold reduction: 31 shuffles; lane L ends with element n0*16+L
        float v[16];
        {
            int bit = (lane >> 4) & 1;   // fold node dimension
#pragma unroll
            for (int i = 0; i < 16; i++) {
                float give = bit ? acc[0][i] : acc[1][i];
                float keep = bit ? acc[1][i] : acc[0][i];
                v[i] = keep + __shfl_xor_sync(0xFFFFFFFFu, give, 16);
            }
        }
#pragma unroll
        for (int o = 8; o >= 1; o >>= 1) {   // fold c bits 3..0
            int bit = (lane / o) & 1;
#pragma unroll
            for (int i = 0; i < o; i++) {
                float give = bit ? v[i] : v[i + o];
                float keep = bit ? v[i + o] : v[i];
                v[i] = keep + __shfl_xor_sync(0xFFFFFFFFu, give, o);
            }
        }
        // ts raw for S6; out gets self-loop + bias folded in
        float dvn = __shfl_sync(0xFFFFFFFFu, dv, (lane >> 4) << 2);
        float ts = dvn * v[0];
        ((float*)g_t)[(size_t)n0 * OUTF + lane] = ts;          // coalesced 128B
        out[(size_t)n0 * OUTF + lane] = dvn * ts + cv_lane;    // dinv*ts + cvec
    }
    grid_sync(3);

    // ===== S6: out[d] += dinv[d]*ts[s]  (quad-level items) =================
    for (int it = gid; it < NE * 4; it += NT) {
        int e = it >> 2, q = it & 3;
        int s = g[e], d = g[NE + e];
        float dvd = __ldcg(&g_dinv[d]);
        float4 v = __ldcg(&g_t[s * 4 + q]);
        redv4((float*)(out + (size_t)d * OUTF + q * 4),
              make_float4(dvd * v.x, dvd * v.y, dvd * v.z, dvd * v.w));
    }
}

// ---------------------------------------------------------------- launch
extern "C" void kernel_launch(void* const* d_in, const int* in_sizes, int n_in,
                              void* d_out, int out_size) {
    const float* x  = (const float*)d_in[0];
    const int*   g  = (const int*)d_in[1];
    const float* W1 = (const float*)d_in[2];
    const float* b1 = (const float*)d_in[3];
    const float* W2 = (const float*)d_in[4];
    const float* b2 = (const float*)d_in[5];
    const float* Wl = (const float*)d_in[6];
    const float* bl = (const float*)d_in[7];
    float* out = (float*)d_out;

    cudaFuncSetAttribute(gcn_persistent,
                         cudaFuncAttributeMaxDynamicSharedMemorySize, 65536);
    gcn_persistent<<<GRID, BLK, 65536>>>(x, g, W1, b1, W2, b2, Wl, bl, out);
}